// round 6
// baseline (speedup 1.0000x reference)
#include <cuda_runtime.h>

// B=8, MSP=2048, D=512, A=64, NB=5
// Exact contraction reordering:
//   Wc[n,d]   = W_fl[n,d] + W_fl[n,512+d]
//   S[n]      = sum_d Wc[n,d]
//   t[b,s,n]  = sum_d e[b,s,d] * Wc[n,d]        (stored transposed: g_tT[n][b*MSP+s])
//   out[b,a,n]= sum_s W_ll[a,s] * t[b,s,n] + b_ll[a]*S[n] + b_fl[n]
//   final[b,i,j,n] = out[b,i,n]

#define NROWS  16384      // B * MSP
#define DVAL   512
#define NB     5
#define AVAL   64
#define BVAL   8
#define MSP    2048

__device__ float g_S[NB];
__device__ float g_tT[NB * NROWS];         // transposed scratch, 320 KB (L2-resident)

// Packed f32x2 FMA (Blackwell): d = a*b + c elementwise on packed pairs.
__device__ __forceinline__ unsigned long long fma2(unsigned long long a,
                                                   unsigned long long b,
                                                   unsigned long long c) {
    unsigned long long d;
    asm("fma.rn.f32x2 %0, %1, %2, %3;" : "=l"(d) : "l"(a), "l"(b), "l"(c));
    return d;
}
__device__ __forceinline__ float unpack_add(unsigned long long v) {
    float lo, hi;
    asm("mov.b64 {%0, %1}, %2;" : "=f"(lo), "=f"(hi) : "l"(v));
    return lo + hi;
}

// ---------------------------------------------------------------------------
// Kernel 1: t. One warp per row, software-pipelined, FFMA2 inner product.
// 192 threads (6 warps), 2 blocks/SM -> up to 170 regs/thread.
// ---------------------------------------------------------------------------
__global__ __launch_bounds__(192, 2) void t_kernel(const float* __restrict__ e,
                                                   const float* __restrict__ W_fl) {
    __shared__ __align__(16) float wcs[NB * DVAL];   // 10 KB
    const int tid  = threadIdx.x;
    const int lane = tid & 31;
    const int warp = tid >> 5;

    for (int i = tid; i < NB * DVAL; i += 192) {
        int n = i / DVAL, d = i - n * DVAL;
        wcs[i] = W_fl[n * 1024 + d] + W_fl[n * 1024 + 512 + d];
    }
    __syncthreads();

    if (blockIdx.x == 0 && warp == 0) {
        #pragma unroll
        for (int n = 0; n < NB; n++) {
            float s = 0.f;
            for (int d = lane; d < DVAL; d += 32) s += wcs[n * DVAL + d];
            #pragma unroll
            for (int off = 16; off > 0; off >>= 1)
                s += __shfl_xor_sync(0xFFFFFFFFu, s, off);
            if (lane == 0) g_S[n] = s;
        }
    }

    // Per-lane Wc as packed f32x2 pairs: lane owns d = r*128 + lane*4 .. +3
    ulonglong2 wc2[4][NB];
    #pragma unroll
    for (int r = 0; r < 4; r++)
        #pragma unroll
        for (int n = 0; n < NB; n++)
            wc2[r][n] = *(const ulonglong2*)&wcs[n * DVAL + r * 128 + lane * 4];

    const int gw = blockIdx.x * 6 + warp;
    const int nw = gridDim.x * 6;

    int row = gw;
    ulonglong2 ev[4];
    if (row < NROWS) {
        const ulonglong2* er = (const ulonglong2*)(e + (size_t)row * DVAL);
        #pragma unroll
        for (int r = 0; r < 4; r++) ev[r] = er[r * 32 + lane];
    }

    while (row < NROWS) {
        const int nxt = row + nw;

        ulonglong2 ev2[4];
        if (nxt < NROWS) {
            const ulonglong2* er2 = (const ulonglong2*)(e + (size_t)nxt * DVAL);
            #pragma unroll
            for (int r = 0; r < 4; r++) ev2[r] = er2[r * 32 + lane];
        }

        unsigned long long acc2[NB];
        #pragma unroll
        for (int n = 0; n < NB; n++) acc2[n] = 0ull;

        #pragma unroll
        for (int r = 0; r < 4; r++) {
            #pragma unroll
            for (int n = 0; n < NB; n++) {
                acc2[n] = fma2(ev[r].x, wc2[r][n].x, acc2[n]);
                acc2[n] = fma2(ev[r].y, wc2[r][n].y, acc2[n]);
            }
        }

        float acc[NB];
        #pragma unroll
        for (int n = 0; n < NB; n++) acc[n] = unpack_add(acc2[n]);

        #pragma unroll
        for (int n = 0; n < NB; n++) {
            #pragma unroll
            for (int off = 16; off > 0; off >>= 1)
                acc[n] += __shfl_xor_sync(0xFFFFFFFFu, acc[n], off);
        }

        // Transposed store: lane n writes g_tT[n][row]
        if (lane < NB) {
            float v = (lane == 0) ? acc[0] : (lane == 1) ? acc[1] :
                      (lane == 2) ? acc[2] : (lane == 3) ? acc[3] : acc[4];
            g_tT[lane * NROWS + row] = v;
        }

        #pragma unroll
        for (int r = 0; r < 4; r++) ev[r] = ev2[r];
        row = nxt;
    }
}

// ---------------------------------------------------------------------------
// Kernel 2: out + broadcast. grid = (16 a-quads, 8 b) = 128 blocks,
// 256 threads (8 warps). Warp w handles s-chunk w*256 for all 4 a's of the
// block; t reads are coalesced from transposed layout. 4x reuse of t per read.
// ---------------------------------------------------------------------------
__global__ __launch_bounds__(256) void out_kernel(const float* __restrict__ W_ll,
                                                  const float* __restrict__ b_ll,
                                                  const float* __restrict__ b_fl,
                                                  float* __restrict__ out) {
    __shared__ float partial[8][4 * NB];
    __shared__ float v[4 * NB];
    const int a0   = blockIdx.x * 4;
    const int b    = blockIdx.y;
    const int tid  = threadIdx.x;
    const int lane = tid & 31;
    const int w    = tid >> 5;
    const int sbase = w * 256;

    // Coalesced front-batched loads: 4 W_ll rows (8 each) + 5 t planes (8 each)
    float wv[4][8];
    #pragma unroll
    for (int al = 0; al < 4; al++) {
        const float* wrow = W_ll + (size_t)(a0 + al) * MSP + sbase;
        #pragma unroll
        for (int k = 0; k < 8; k++) wv[al][k] = wrow[lane + 32 * k];
    }
    float tv[NB][8];
    #pragma unroll
    for (int n = 0; n < NB; n++) {
        const float* tp = g_tT + (size_t)n * NROWS + (size_t)b * MSP + sbase;
        #pragma unroll
        for (int k = 0; k < 8; k++) tv[n][k] = tp[lane + 32 * k];
    }

    float acc[4][NB];
    #pragma unroll
    for (int al = 0; al < 4; al++)
        #pragma unroll
        for (int n = 0; n < NB; n++) acc[al][n] = 0.f;

    #pragma unroll
    for (int k = 0; k < 8; k++)
        #pragma unroll
        for (int al = 0; al < 4; al++)
            #pragma unroll
            for (int n = 0; n < NB; n++)
                acc[al][n] += wv[al][k] * tv[n][k];

    #pragma unroll
    for (int al = 0; al < 4; al++)
        #pragma unroll
        for (int n = 0; n < NB; n++)
            #pragma unroll
            for (int off = 16; off > 0; off >>= 1)
                acc[al][n] += __shfl_xor_sync(0xFFFFFFFFu, acc[al][n], off);

    if (lane == 0) {
        #pragma unroll
        for (int al = 0; al < 4; al++)
            #pragma unroll
            for (int n = 0; n < NB; n++)
                partial[w][al * NB + n] = acc[al][n];
    }
    __syncthreads();

    if (tid < 4 * NB) {
        const int al = tid / NB, n = tid - al * NB;
        float s = 0.f;
        #pragma unroll
        for (int q = 0; q < 8; q++) s += partial[q][tid];
        v[tid] = s + b_ll[a0 + al] * g_S[n] + b_fl[n];
    }
    __syncthreads();

    // Broadcast over j: 4 a's x 64 j x 5 n = 1280 contiguous floats
    float* base = out + ((size_t)(b * AVAL + a0)) * (AVAL * NB);
    #pragma unroll
    for (int k = 0; k < 5; k++) {
        const int idx = tid + k * 256;
        const int al  = idx / (AVAL * NB);
        const int n   = idx % NB;
        base[idx] = v[al * NB + n];
    }
}

// ---------------------------------------------------------------------------
extern "C" void kernel_launch(void* const* d_in, const int* in_sizes, int n_in,
                              void* d_out, int out_size) {
    const float* e    = (const float*)d_in[0];
    const float* W_ll = (const float*)d_in[1];
    const float* b_ll = (const float*)d_in[2];
    const float* W_fl = (const float*)d_in[3];
    const float* b_fl = (const float*)d_in[4];
    float* out = (float*)d_out;

    t_kernel<<<296, 192>>>(e, W_fl);
    out_kernel<<<dim3(16, BVAL), 256>>>(W_ll, b_ll, b_fl, out);
}